// round 7
// baseline (speedup 1.0000x reference)
#include <cuda_runtime.h>

// Problem constants (shapes fixed by reference setup_inputs)
#define BB 8
#define HH 256
#define WW 256
#define KK 9
#define PADR 4
#define NPATCH 81            // K*K, C=1
#define NPIX (BB*HH*WW)      // 524288

// Patch kernel tiling: 16x8 pixels per block, 2 threads per pixel.
#define TX 16
#define TY 8
#define NTHREADS (TX*TY*2)               // 256
#define HX (TX + 2*PADR)                 // 24
#define HY (TY + 2*PADR)                 // 16
#define GX (WW/TX)                       // 16
#define GY (HH/TY)                       // 32
#define NBLOCKS (GX*GY*BB)               // 4096

// Scratch (no allocations allowed -> __device__ globals)
__device__ float2 g_row[NPIX];      // horizontal 9-window sums (pred, targ)
__device__ float2 g_dist[NPIX];     // packed (pred_dist, targ_dist)
__device__ float  g_partials[NBLOCKS];

// ---------------------------------------------------------------------------
// Scalar compare-exchange -> 2x FMNMX in SASS
// ---------------------------------------------------------------------------
__device__ __forceinline__ void ce(float& a, float& b) {
    float mn = fminf(a, b);
    float mx = fmaxf(a, b);
    a = mn; b = mx;
}

// ---------------------------------------------------------------------------
// Phase 1a: horizontal clipped 9-window sums for both tensors
// ---------------------------------------------------------------------------
__global__ void rowsum_kernel(const float* __restrict__ pred,
                              const float* __restrict__ targ) {
    int idx = blockIdx.x * blockDim.x + threadIdx.x;
    if (idx >= NPIX) return;
    int x = idx & (WW - 1);
    int rowbase = idx - x;
    int x0 = max(x - PADR, 0);
    int x1 = min(x + PADR, WW - 1);
    float sp = 0.f, st = 0.f;
    for (int xx = x0; xx <= x1; ++xx) {
        sp += pred[rowbase + xx];
        st += targ[rowbase + xx];
    }
    g_row[idx] = make_float2(sp, st);
}

// ---------------------------------------------------------------------------
// Phase 1b: vertical clipped sums, divide by valid count
// (count_include_pad=False), dist = x - avg, write packed float2
// ---------------------------------------------------------------------------
__global__ void dist_kernel(const float* __restrict__ pred,
                            const float* __restrict__ targ) {
    int idx = blockIdx.x * blockDim.x + threadIdx.x;
    if (idx >= NPIX) return;
    int x = idx & (WW - 1);
    int y = (idx >> 8) & (HH - 1);
    int planebase = idx - y * WW - x;
    int y0 = max(y - PADR, 0);
    int y1 = min(y + PADR, HH - 1);
    float sp = 0.f, st = 0.f;
    for (int yy = y0; yy <= y1; ++yy) {
        float2 r = g_row[planebase + yy * WW + x];
        sp += r.x; st += r.y;
    }
    int x0 = max(x - PADR, 0);
    int x1 = min(x + PADR, WW - 1);
    float inv = 1.0f / (float)((y1 - y0 + 1) * (x1 - x0 + 1));
    float2 d;
    d.x = pred[idx] - sp * inv;
    d.y = targ[idx] - st * inv;
    g_dist[idx] = d;
}

// ---------------------------------------------------------------------------
// Phase 2: per-pixel sort of both 81-element patches + SSE accumulation.
// Two threads per pixel: even lane handles pred, odd lane handles targ.
// Each thread runs ONE 81-element Batcher network (~81 live regs, no spills).
// Cross pairing via __shfl_xor(.,1) between the adjacent lanes of the pair.
// ---------------------------------------------------------------------------
__global__ __launch_bounds__(NTHREADS)
void patch_kernel() {
    // Interleaved halo: [hy][hx][which] -> a warp's 32 lanes (16 pixels x 2
    // roles) read 32 consecutive 4B words per (dy,dx) -> conflict-free LDS.
    __shared__ float halo[HY][HX * 2];
    __shared__ float red[NTHREADS];

    int b   = blockIdx.z;
    int bx0 = blockIdx.x * TX;
    int by0 = blockIdx.y * TY;
    int t   = threadIdx.x;

    // Load halo as float2 straight from packed g_dist. Out-of-image -> 0,
    // which exactly reproduces nn.Unfold's zero padding inside the patches.
#pragma unroll
    for (int i = t; i < HX * HY; i += NTHREADS) {
        int hx = i % HX, hy = i / HX;
        int gx = bx0 + hx - PADR;
        int gy = by0 + hy - PADR;
        float2 v = make_float2(0.f, 0.f);
        if (gx >= 0 && gx < WW && gy >= 0 && gy < HH)
            v = g_dist[(b * HH + gy) * WW + gx];
        *reinterpret_cast<float2*>(&halo[hy][hx * 2]) = v;
    }
    __syncthreads();

    int which = t & 1;        // 0 = pred, 1 = targ
    int pix   = t >> 1;       // 0..127
    int lx    = pix % TX;
    int ly    = pix / TX;

    // Gather this thread's 81 patch values into registers.
    float v[NPATCH];
#pragma unroll
    for (int dy = 0; dy < KK; ++dy)
#pragma unroll
        for (int dx = 0; dx < KK; ++dx)
            v[dy * KK + dx] = halo[ly + dy][(lx + dx) * 2 + which];

    // Batcher odd-even mergesort network for arbitrary n=81. All indices are
    // compile-time constants -> straight-line FMNMX code, pure register file.
    // (Canonical arbitrary-n form: the i<k loop with the i+j+k<n guard is
    // min(k, n-j-k); the /(2p) block test selects valid pairs.)
#pragma unroll
    for (int p = 1; p < NPATCH; p <<= 1) {
#pragma unroll
        for (int k = p; k >= 1; k >>= 1) {
#pragma unroll
            for (int j = k % p; j + k < NPATCH; j += 2 * k) {
#pragma unroll
                for (int i = 0; i < k; ++i) {
                    if (i + j + k < NPATCH) {
                        if ((i + j) / (2 * p) == (i + j + k) / (2 * p)) {
                            ce(v[i + j], v[i + j + k]);
                        }
                    }
                }
            }
        }
    }

    // Pair epilogue: partner lane (same pixel, other tensor) holds the other
    // sorted array at identical ranks. Both lanes compute the same sum of
    // squared rank-wise diffs; only the even lane contributes it.
    float acc = 0.f;
#pragma unroll
    for (int r = 0; r < NPATCH; ++r) {
        float o = __shfl_xor_sync(0xffffffffu, v[r], 1);
        float d = v[r] - o;
        acc = fmaf(d, d, acc);
    }

    // Deterministic block reduction -> per-block partial.
    red[t] = (which == 0) ? acc : 0.f;
    __syncthreads();
#pragma unroll
    for (int s = NTHREADS / 2; s > 0; s >>= 1) {
        if (t < s) red[t] += red[t + s];
        __syncthreads();
    }
    if (t == 0) {
        int bid = (blockIdx.z * gridDim.y + blockIdx.y) * gridDim.x + blockIdx.x;
        g_partials[bid] = red[0];
    }
}

// ---------------------------------------------------------------------------
// Phase 3: deterministic final reduction (double accumulation), write mean.
// ---------------------------------------------------------------------------
__global__ void reduce_kernel(float* __restrict__ out) {
    __shared__ double s[256];
    int t = threadIdx.x;
    double acc = 0.0;
    for (int i = t; i < NBLOCKS; i += 256) acc += (double)g_partials[i];
    s[t] = acc;
    __syncthreads();
    for (int st = 128; st > 0; st >>= 1) {
        if (t < st) s[t] += s[t + st];
        __syncthreads();
    }
    if (t == 0) {
        double denom = (double)NPIX * (double)NPATCH;
        out[0] = (float)(s[0] / denom);
    }
}

// ---------------------------------------------------------------------------
extern "C" void kernel_launch(void* const* d_in, const int* in_sizes, int n_in,
                              void* d_out, int out_size) {
    const float* pred = (const float*)d_in[0];
    const float* targ = (const float*)d_in[1];
    float* out = (float*)d_out;

    int threads = 256;
    int blocks1 = (NPIX + threads - 1) / threads;
    rowsum_kernel<<<blocks1, threads>>>(pred, targ);
    dist_kernel<<<blocks1, threads>>>(pred, targ);

    dim3 grid(GX, GY, BB);
    patch_kernel<<<grid, NTHREADS>>>();

    reduce_kernel<<<1, 256>>>(out);
}